// round 8
// baseline (speedup 1.0000x reference)
#include <cuda_runtime.h>
#include <cuda_fp16.h>

#define D 96
#define HP 128                             // padded fp16 row (256B, 2 lines)
#define NMAX 50000
#define EMAX 800000
#define SCAN_B 512
#define NSCANBLK ((NMAX + SCAN_B - 1) / SCAN_B)   // 98

typedef unsigned long long ull;

// ---------------- scratch (static device globals; no allocation) ----------
__device__ int    g_counts[NMAX];          // zero at load; re-zeroed by k_scanall
__device__ int    g_rowptr[NMAX + 1];
__device__ int    g_cursor[NMAX];
__device__ float  g_dinv[NMAX];
__device__ int4   g_adj4[EMAX / 2 + 1];    // pairs of {src, bitcast(norm)}
__device__ __half g_hh[(size_t)NMAX * HP]; // GEMM out, fp16 padded; pad stays 0
__device__ float  g_h2[(size_t)NMAX * D];  // agg out / GEMM2 in (fp32)
__device__ int    g_blockSums[NSCANBLK + 2];
__device__ int    g_bar1, g_bar2;          // grid barrier counters (reset by agg1)

// ---------------- packed f32x2 helpers -------------------------------------
__device__ __forceinline__ ull pack2(float lo, float hi) {
    ull r; asm("mov.b64 %0, {%1, %2};" : "=l"(r) : "f"(lo), "f"(hi)); return r;
}
__device__ __forceinline__ void unpack2(ull v, float& lo, float& hi) {
    asm("mov.b64 {%0, %1}, %2;" : "=f"(lo), "=f"(hi) : "l"(v));
}
__device__ __forceinline__ void ffma2(ull& d, ull a, ull b) {
    asm("fma.rn.f32x2 %0, %1, %2, %0;" : "+l"(d) : "l"(a), "l"(b));
}

// ---------------- fused scan + scatter (two grid barriers, 98 blocks) ------
__global__ __launch_bounds__(SCAN_B) void k_scanall(const int* __restrict__ ei,
                                                    int n, int nb, int E) {
    __shared__ int wsum[16];
    __shared__ int sbase;
    int tidb = threadIdx.x;
    int i = blockIdx.x * SCAN_B + tidb;
    int lane = tidb & 31, wid = tidb >> 5;

    // phase A: read counts, dinv, re-zero counts, block-local exclusive scan
    int v = 0;
    if (i < n) {
        v = g_counts[i];
        g_dinv[i] = rsqrtf((float)(v + 1));   // +1 self loop
        g_counts[i] = 0;                      // restore invariant
    }
    int x = v;
#pragma unroll
    for (int o = 1; o < 32; o <<= 1) {
        int t = __shfl_up_sync(0xFFFFFFFFu, x, o);
        if (lane >= o) x += t;
    }
    if (lane == 31) wsum[wid] = x;
    __syncthreads();
    if (wid == 0) {
        int s = (lane < 16) ? wsum[lane] : 0;
#pragma unroll
        for (int o = 1; o < 16; o <<= 1) {
            int t = __shfl_up_sync(0xFFFFFFFFu, s, o);
            if (lane >= o) s += t;
        }
        if (lane < 16) wsum[lane] = s;
    }
    __syncthreads();
    int wbase = (wid > 0) ? wsum[wid - 1] : 0;
    if (i < n) g_rowptr[i] = wbase + x - v;          // block-local exclusive
    if (tidb == SCAN_B - 1) g_blockSums[blockIdx.x] = wbase + x;
    __threadfence();
    __syncthreads();

    // grid barrier 1
    if (tidb == 0) {
        atomicAdd(&g_bar1, 1);
        while (*(volatile int*)&g_bar1 < nb) { }
    }
    __syncthreads();

    // phase B: cross-block prefix, finalize rowptr + cursor
    if (wid == 0) {
        int acc = 0;
        for (int b = lane; b < blockIdx.x; b += 32) acc += g_blockSums[b];
#pragma unroll
        for (int o = 16; o; o >>= 1) acc += __shfl_xor_sync(0xFFFFFFFFu, acc, o);
        if (lane == 0) sbase = acc;
    }
    __syncthreads();
    int rbase = sbase;
    if (i < n) {
        int val = g_rowptr[i] + rbase;
        g_rowptr[i] = val;
        g_cursor[i] = val;
    }
    if (blockIdx.x == nb - 1 && tidb == 0)
        g_rowptr[n] = rbase + g_blockSums[nb - 1];   // total = E
    __threadfence();
    __syncthreads();

    // grid barrier 2
    if (tidb == 0) {
        atomicAdd(&g_bar2, 1);
        while (*(volatile int*)&g_bar2 < nb) { }
    }
    __syncthreads();

    // phase C: scatter edges into CSR
    int2* adj = (int2*)g_adj4;
    int stride = nb * SCAN_B;
    for (int e = blockIdx.x * SCAN_B + tidb; e < E; e += stride) {
        int s = ei[e];
        int d = ei[E + e];
        int pos = atomicAdd(&g_cursor[d], 1);
        float norm = g_dinv[s] * g_dinv[d];
        adj[pos] = make_int2(s, __float_as_int(norm));
    }
}

// ---------------- dense GEMM: Hh[N,HP] = X[N,96] @ W[96,96] (fp16 out) -----
// Register tile per thread: 4 contiguous features x 2 row-pairs (f32x2 packed).
// block: 192 threads, TM=32 nodes. tid -> f0=(tid%24)*4, p0=(tid/24)*2.
// src_sel: 0 = Xext (fp32), 1 = g_h2 (fp32). Output: g_hh (fp16, stride HP).
// histE > 0: also grid-stride degree histogram over edge dst (fused hist).
#define TM 32
__global__ __launch_bounds__(192) void k_gemm(const float* __restrict__ Xext,
                                              const float* __restrict__ W,
                                              int n, int src_sel,
                                              const int* __restrict__ ei,
                                              int histE) {
    __shared__ __align__(16) float Ws[96 * 96];
    __shared__ __align__(16) ull Xs2[16][96];   // Xs2[p][k] = {X[2p][k], X[2p+1][k]}
    const float* X = src_sel ? (const float*)g_h2 : Xext;
    __half* Y = (__half*)g_hh;

    int tid = threadIdx.x;

    // fused degree histogram (layer-1 launch only); independent of GEMM work
    if (histE > 0) {
        int stride = gridDim.x * blockDim.x;
        for (int e = blockIdx.x * blockDim.x + tid; e < histE; e += stride)
            atomicAdd(&g_counts[ei[histE + e]], 1);
    }

    {
        const float4* Wv = (const float4*)W;
        float4* Wsv = (float4*)Ws;
        for (int i = tid; i < 96 * 96 / 4; i += 192) Wsv[i] = Wv[i];
    }

    int n0 = blockIdx.x * TM;
    int rows = min(TM, n - n0);
    float* Xsf = (float*)&Xs2[0][0];
    for (int i = tid; i < TM * 96; i += 192) {
        int m = i / 96, k = i % 96;     // coalesced global read
        float v = (m < rows) ? X[(size_t)(n0 + m) * 96 + k] : 0.f;
        Xsf[((m >> 1) * 96 + k) * 2 + (m & 1)] = v;
    }
    __syncthreads();

    int f0 = (tid % 24) * 4;
    int p0 = (tid / 24) * 2;

    ull acc[4][2];
#pragma unroll
    for (int f = 0; f < 4; f++)
#pragma unroll
        for (int p = 0; p < 2; p++) acc[f][p] = 0ull;

#pragma unroll 6
    for (int k = 0; k < 96; k += 2) {
        float4 w0 = *(const float4*)&Ws[k * 96 + f0];
        float4 w1 = *(const float4*)&Ws[(k + 1) * 96 + f0];
        ulonglong2 x0 = *(const ulonglong2*)&Xs2[p0][k];
        ulonglong2 x1 = *(const ulonglong2*)&Xs2[p0 + 1][k];

        ull pw00 = pack2(w0.x, w0.x), pw01 = pack2(w0.y, w0.y);
        ull pw02 = pack2(w0.z, w0.z), pw03 = pack2(w0.w, w0.w);
        ull pw10 = pack2(w1.x, w1.x), pw11 = pack2(w1.y, w1.y);
        ull pw12 = pack2(w1.z, w1.z), pw13 = pack2(w1.w, w1.w);

        ffma2(acc[0][0], x0.x, pw00); ffma2(acc[1][0], x0.x, pw01);
        ffma2(acc[2][0], x0.x, pw02); ffma2(acc[3][0], x0.x, pw03);
        ffma2(acc[0][0], x0.y, pw10); ffma2(acc[1][0], x0.y, pw11);
        ffma2(acc[2][0], x0.y, pw12); ffma2(acc[3][0], x0.y, pw13);

        ffma2(acc[0][1], x1.x, pw00); ffma2(acc[1][1], x1.x, pw01);
        ffma2(acc[2][1], x1.x, pw02); ffma2(acc[3][1], x1.x, pw03);
        ffma2(acc[0][1], x1.y, pw10); ffma2(acc[1][1], x1.y, pw11);
        ffma2(acc[2][1], x1.y, pw12); ffma2(acc[3][1], x1.y, pw13);
    }

#pragma unroll
    for (int p = 0; p < 2; p++) {
        int m0 = (p0 + p) * 2;
        float4 lo4, hi4;
        unpack2(acc[0][p], lo4.x, hi4.x);
        unpack2(acc[1][p], lo4.y, hi4.y);
        unpack2(acc[2][p], lo4.z, hi4.z);
        unpack2(acc[3][p], lo4.w, hi4.w);
        if (n0 + m0 < n) {
            __half* yr = Y + (size_t)(n0 + m0) * HP + f0;
            *(__half2*)yr       = __floats2half2_rn(lo4.x, lo4.y);
            *(__half2*)(yr + 2) = __floats2half2_rn(lo4.z, lo4.w);
        }
        if (n0 + m0 + 1 < n) {
            __half* yr = Y + (size_t)(n0 + m0 + 1) * HP + f0;
            *(__half2*)yr       = __floats2half2_rn(hi4.x, hi4.y);
            *(__half2*)(yr + 2) = __floats2half2_rn(hi4.z, hi4.w);
        }
    }
}

// ---------------- aggregation: one warp per node ---------------------------
// reads g_hh (fp16, stride HP); writes g_h2 (dst_sel=0) or out (dst_sel=1).
// lane handles features {2L,2L+1} and (lane<16) {64+2L,65+2L}; lanes>=16's
// second half2 load lands in the zero pad -> contributes 0. 2 LDG/edge for
// features + 1 LDG.128 per 2 edges for adjacency.
__global__ __launch_bounds__(256) void k_agg(const float* __restrict__ bias,
                                             const float* __restrict__ aptr,
                                             float* __restrict__ outExt,
                                             int n, int do_prelu, int dst_sel,
                                             int reset_bar) {
    if (reset_bar && blockIdx.x == 0 && threadIdx.x == 0) {
        g_bar1 = 0; g_bar2 = 0;               // for next replay's k_scanall
    }
    int warp = (blockIdx.x * blockDim.x + threadIdx.x) >> 5;
    int lane = threadIdx.x & 31;
    if (warp >= n) return;

    const __half2* hb = (const __half2*)g_hh;       // 64 half2 per row
    float* out = dst_sel ? outExt : (float*)g_h2;

    float dn = g_dinv[warp];
    float dn2 = dn * dn;
    const __half2* hr = hb + (size_t)warp * (HP / 2);
    float2 s0 = __half22float2(hr[lane]);
    float2 s1 = __half22float2(hr[32 + lane]);
    float a00 = s0.x * dn2, a01 = s0.y * dn2;
    float a10 = s1.x * dn2, a11 = s1.y * dn2;

    int e = g_rowptr[warp];
    int end = g_rowptr[warp + 1];
    const int2* adj = (const int2*)g_adj4;

    if ((e & 1) && e < end) {                 // align to int4 pairs
        int2 q = adj[e];
        const __half2* r = hb + (size_t)q.x * (HP / 2);
        float nn = __int_as_float(q.y);
        float2 u0 = __half22float2(r[lane]);
        float2 u1 = __half22float2(r[32 + lane]);
        a00 = fmaf(u0.x, nn, a00); a01 = fmaf(u0.y, nn, a01);
        a10 = fmaf(u1.x, nn, a10); a11 = fmaf(u1.y, nn, a11);
        e++;
    }
    for (; e + 1 < end; e += 2) {
        int4 q = *(const int4*)(adj + e);     // 2 edges, one broadcast LDG.128
        const __half2* r0 = hb + (size_t)q.x * (HP / 2);
        const __half2* r1 = hb + (size_t)q.z * (HP / 2);
        float n0 = __int_as_float(q.y);
        float n1 = __int_as_float(q.w);
        float2 u0 = __half22float2(r0[lane]);
        float2 u1 = __half22float2(r0[32 + lane]);
        float2 w0 = __half22float2(r1[lane]);
        float2 w1 = __half22float2(r1[32 + lane]);
        a00 = fmaf(u0.x, n0, a00); a01 = fmaf(u0.y, n0, a01);
        a10 = fmaf(u1.x, n0, a10); a11 = fmaf(u1.y, n0, a11);
        a00 = fmaf(w0.x, n1, a00); a01 = fmaf(w0.y, n1, a01);
        a10 = fmaf(w1.x, n1, a10); a11 = fmaf(w1.y, n1, a11);
    }
    if (e < end) {
        int2 q = adj[e];
        const __half2* r = hb + (size_t)q.x * (HP / 2);
        float nn = __int_as_float(q.y);
        float2 u0 = __half22float2(r[lane]);
        float2 u1 = __half22float2(r[32 + lane]);
        a00 = fmaf(u0.x, nn, a00); a01 = fmaf(u0.y, nn, a01);
        a10 = fmaf(u1.x, nn, a10); a11 = fmaf(u1.y, nn, a11);
    }

    const float2* b2 = (const float2*)bias;
    float2 bb0 = b2[lane];
    a00 += bb0.x; a01 += bb0.y;
    if (lane < 16) {
        float2 bb1 = b2[32 + lane];
        a10 += bb1.x; a11 += bb1.y;
    }
    if (do_prelu) {
        float a = aptr[0];
        a00 = (a00 > 0.f) ? a00 : a * a00;
        a01 = (a01 > 0.f) ? a01 : a * a01;
        a10 = (a10 > 0.f) ? a10 : a * a10;
        a11 = (a11 > 0.f) ? a11 : a * a11;
    }
    float2* o2 = (float2*)(out + (size_t)warp * 96);
    o2[lane] = make_float2(a00, a01);
    if (lane < 16) o2[32 + lane] = make_float2(a10, a11);
}

// ---------------- launch ---------------------------------------------------
extern "C" void kernel_launch(void* const* d_in, const int* in_sizes, int n_in,
                              void* d_out, int out_size) {
    const float* x  = (const float*)d_in[0];
    const int*   ei = (const int*)d_in[1];      // int32! (JAX x64 disabled)
    const float* W1 = (const float*)d_in[2];
    const float* b1 = (const float*)d_in[3];
    const float* a1 = (const float*)d_in[4];
    const float* W2 = (const float*)d_in[5];
    const float* b2 = (const float*)d_in[6];
    float*       out = (float*)d_out;

    int N = in_sizes[0] / D;
    int E = in_sizes[1] / 2;

    int nscan = (N + SCAN_B - 1) / SCAN_B;
    int gemm_blocks = (N + TM - 1) / TM;
    int agg_blocks = (N * 32 + 255) / 256;

    // 1) GEMM1 with fused degree histogram
    k_gemm<<<gemm_blocks, 192>>>(x, W1, N, 0, ei, E);
    // 2) fused scan (dinv, rowptr, cursor) + scatter, grid barriers inside
    k_scanall<<<nscan, SCAN_B>>>(ei, N, nscan, E);
    // 3) layer-1 aggregate + PReLU -> g_h2 (also resets barrier counters)
    k_agg<<<agg_blocks, 256>>>(b1, a1, out, N, 1, 0, 1);
    // 4) GEMM2: g_h2 @ W2 -> g_hh
    k_gemm<<<gemm_blocks, 192>>>(x /*unused*/, W2, N, 1, ei, 0);
    // 5) layer-2 aggregate -> out
    k_agg<<<agg_blocks, 256>>>(b2, a1, out, N, 0, 1, 0);
}